// round 1
// baseline (speedup 1.0000x reference)
#include <cuda_runtime.h>
#include <cuda_bf16.h>
#include <math.h>

// ---------------- problem constants ----------------
#define Bn 4
#define Qn 900
#define Kn 1024
#define En 256
#define Hn 8
#define Dn 32
#define CPBH 64
#define QT 8
#define KT 32
#define SCALE_Q 0.17677669529663687f  // 1/sqrt(32)

// ---------------- scratch (device globals; no allocation allowed) ----------------
__device__ __align__(16) float g_q[Bn * Qn * En];
__device__ __align__(16) float g_k[Bn * Kn * En];
__device__ __align__(16) float g_v[Bn * Kn * En];
__device__ __align__(16) float g_att[Bn * Qn * En];

// ---------------- generic projection GEMM: C[m,n] = scale*(sum_k A[m,k]*W[n,k] + bias[n]) ----------------
// A: [M,256], W: [256,256] (row n gives weights), C: [M,256]. Tile 64x64, 256 threads, 4x4 micro-tile.
__global__ __launch_bounds__(256) void proj_gemm(
    const float* __restrict__ A, const float* __restrict__ W,
    const float* __restrict__ bias, float* __restrict__ C,
    int M, float scale)
{
    __shared__ __align__(16) float As[16][64];
    __shared__ __align__(16) float Bs[16][64];

    const int m0 = blockIdx.x * 64;
    const int n0 = blockIdx.y * 64;
    const int t  = threadIdx.x;
    const int tx = t & 15;        // n micro index
    const int ty = t >> 4;        // m micro index
    const int lr = t >> 2;        // 0..63 row for loads
    const int lc = (t & 3) * 4;   // col group for loads

    float acc[4][4];
#pragma unroll
    for (int i = 0; i < 4; i++)
#pragma unroll
        for (int j = 0; j < 4; j++) acc[i][j] = 0.f;

    for (int k0 = 0; k0 < 256; k0 += 16) {
        float4 a4 = make_float4(0.f, 0.f, 0.f, 0.f);
        if (m0 + lr < M)
            a4 = *(const float4*)&A[(size_t)(m0 + lr) * 256 + k0 + lc];
        As[lc + 0][lr] = a4.x; As[lc + 1][lr] = a4.y;
        As[lc + 2][lr] = a4.z; As[lc + 3][lr] = a4.w;

        float4 b4 = *(const float4*)&W[(size_t)(n0 + lr) * 256 + k0 + lc];
        Bs[lc + 0][lr] = b4.x; Bs[lc + 1][lr] = b4.y;
        Bs[lc + 2][lr] = b4.z; Bs[lc + 3][lr] = b4.w;
        __syncthreads();

#pragma unroll
        for (int kk = 0; kk < 16; kk++) {
            float4 av = *(const float4*)&As[kk][ty * 4];
            float4 bv = *(const float4*)&Bs[kk][tx * 4];
            float am[4] = {av.x, av.y, av.z, av.w};
            float bm[4] = {bv.x, bv.y, bv.z, bv.w};
#pragma unroll
            for (int i = 0; i < 4; i++)
#pragma unroll
                for (int j = 0; j < 4; j++)
                    acc[i][j] = fmaf(am[i], bm[j], acc[i][j]);
        }
        __syncthreads();
    }

#pragma unroll
    for (int i = 0; i < 4; i++) {
        int m = m0 + ty * 4 + i;
        if (m < M) {
            int n = n0 + tx * 4;
            float4 o;
            o.x = scale * (acc[i][0] + bias[n + 0]);
            o.y = scale * (acc[i][1] + bias[n + 1]);
            o.z = scale * (acc[i][2] + bias[n + 2]);
            o.w = scale * (acc[i][3] + bias[n + 3]);
            *(float4*)&C[(size_t)m * 256 + n] = o;
        }
    }
}

// ---------------- fused attention ----------------
// Block: (q-tile of 8, batch). 256 threads. Stream K in tiles of 32.
// SMEM layout (floats):
//   q_s   [8][256]        @ 0       (2048)
//   k_s   [32][260]       @ 2048    (8320)   stride 260 -> conflict-free float4 reads
//   v_t   [256][33]       @ 10368   (8448)   transposed+remapped: row r = d*32 + h*4 + ds
//   s_s   [8][32][8]      @ 18816   (2048)
//   w1    float4[64]      @ 20864   (256)    (Wc1[j,0], Wc1[j,1], bc1[j], 0)
//   w2    [64][8]         @ 21120   (512)    Wc2 transposed: w2[j][h]
//   b2    [8]             @ 21632
//   msk   [32]            @ 21640
#define SM_Q   0
#define SM_K   2048
#define SM_V   10368
#define SM_S   18816
#define SM_W1  20864
#define SM_W2  21120
#define SM_B2  21632
#define SM_MSK 21640
#define SM_FLOATS 21672
#define SM_BYTES (SM_FLOATS * 4)

__global__ __launch_bounds__(256) void attn_kernel(
    const float* __restrict__ rd, const unsigned char* __restrict__ mask,
    const float* __restrict__ Wc1, const float* __restrict__ bc1,
    const float* __restrict__ Wc2, const float* __restrict__ bc2)
{
    extern __shared__ __align__(16) float sm[];
    float*  q_s = sm + SM_Q;
    float*  k_s = sm + SM_K;
    float*  v_t = sm + SM_V;
    float*  s_s = sm + SM_S;
    float4* w1  = (float4*)(sm + SM_W1);
    float*  w2  = sm + SM_W2;
    float*  b2  = sm + SM_B2;
    float*  msk = sm + SM_MSK;

    const int b  = blockIdx.y;
    const int q0 = blockIdx.x * QT;
    const int t  = threadIdx.x;

    // ---- load q tile + CPB weights ----
#pragma unroll
    for (int i = 0; i < 2; i++) {
        int idx = t + i * 256;        // 512 float4 covers 8x256
        int qq  = idx >> 6, e4 = idx & 63;
        float4 val = make_float4(0.f, 0.f, 0.f, 0.f);
        if (q0 + qq < Qn)
            val = *(const float4*)&g_q[(size_t)((b * Qn) + (q0 + qq)) * En + e4 * 4];
        *(float4*)&q_s[qq * 256 + e4 * 4] = val;
    }
    if (t < 64) w1[t] = make_float4(Wc1[2 * t], Wc1[2 * t + 1], bc1[t], 0.f);
    for (int i = t; i < 512; i += 256) {
        int j = i >> 3, h = i & 7;
        w2[j * 8 + h] = Wc2[h * 64 + j];
    }
    if (t < 8) b2[t] = bc2[t];
    __syncthreads();

    // ---- phase-C identity: 4 threads per (q,h), each owns 8 dims ----
    const int cq  = t >> 5;       // query in tile
    const int rem = t & 31;
    const int ch  = rem >> 2;     // head
    const int cds = rem & 3;      // dim-subgroup
    float m_run = -INFINITY, l_run = 0.f;
    float o[8];
#pragma unroll
    for (int d = 0; d < 8; d++) o[d] = 0.f;

    // ---- phase-B identity: one thread per (q, k-lane) ----
    const int sq  = t >> 5;
    const int bkl = t & 31;

    for (int k0 = 0; k0 < Kn; k0 += KT) {
        // ===== Phase A: load K/V tile =====
#pragma unroll
        for (int i = 0; i < 8; i++) {
            int idx = t + i * 256;    // 2048 float4 = 32 rows x 64 float4
            int kk  = idx >> 6, e4 = idx & 63;
            size_t gidx = (size_t)((b * Kn) + (k0 + kk)) * En + e4 * 4;
            float4 kv4 = *(const float4*)&g_k[gidx];
            *(float4*)&k_s[kk * 260 + e4 * 4] = kv4;
            float4 vv = *(const float4*)&g_v[gidx];
            const float* vf = (const float*)&vv;
#pragma unroll
            for (int j = 0; j < 4; j++) {
                int e  = e4 * 4 + j;
                int h  = e >> 5, dd = e & 31;
                int ds = dd >> 3, d = dd & 7;
                int r  = d * 32 + h * 4 + ds;   // remap so lanes hit distinct banks
                v_t[r * 33 + kk] = vf[j];
            }
        }
        if (t < KT) msk[t] = mask[b * Kn + k0 + t] ? 1.f : 0.f;
        __syncthreads();

        // ===== Phase B: CPB MLP (shared across heads) + QK scores =====
        {
            float acc[8];
#pragma unroll
            for (int h = 0; h < 8; h++) acc[h] = b2[h];

            int qg = q0 + sq;
            float dx = 0.f, dy = 0.f;
            if (qg < Qn) {
                const float2 rd2 = *(const float2*)&rd[(((size_t)b * Qn + qg) * Kn + (k0 + bkl)) * 2];
                dx = rd2.x; dy = rd2.y;
            }
#pragma unroll
            for (int j = 0; j < 64; j++) {
                float4 w = w1[j];
                float hj = fmaxf(fmaf(w.x, dx, fmaf(w.y, dy, w.z)), 0.f);
                float4 w2a = *(const float4*)&w2[j * 8];
                float4 w2b = *(const float4*)&w2[j * 8 + 4];
                acc[0] = fmaf(w2a.x, hj, acc[0]);
                acc[1] = fmaf(w2a.y, hj, acc[1]);
                acc[2] = fmaf(w2a.z, hj, acc[2]);
                acc[3] = fmaf(w2a.w, hj, acc[3]);
                acc[4] = fmaf(w2b.x, hj, acc[4]);
                acc[5] = fmaf(w2b.y, hj, acc[5]);
                acc[6] = fmaf(w2b.z, hj, acc[6]);
                acc[7] = fmaf(w2b.w, hj, acc[7]);
            }

            const float* qrow = &q_s[sq * 256];
            const float* krow = &k_s[bkl * 260];
            const bool masked = msk[bkl] != 0.f;
            float sc[8];
#pragma unroll
            for (int h = 0; h < 8; h++) {
                float dot = 0.f;
#pragma unroll
                for (int i = 0; i < 8; i++) {
                    float4 qv = *(const float4*)&qrow[h * 32 + i * 4];
                    float4 kv = *(const float4*)&krow[h * 32 + i * 4];
                    dot = fmaf(qv.x, kv.x, dot);
                    dot = fmaf(qv.y, kv.y, dot);
                    dot = fmaf(qv.z, kv.z, dot);
                    dot = fmaf(qv.w, kv.w, dot);
                }
                sc[h] = masked ? -INFINITY : (dot + acc[h]);
            }
            float* srow = &s_s[sq * 256 + bkl * 8];
            *(float4*)srow       = make_float4(sc[0], sc[1], sc[2], sc[3]);
            *(float4*)(srow + 4) = make_float4(sc[4], sc[5], sc[6], sc[7]);
        }
        __syncthreads();

        // ===== Phase C: online softmax + AV =====
        {
            const float* srow = &s_s[cq * 256 + ch];   // stride 8 across k
            float mt = -INFINITY;
#pragma unroll
            for (int kl = 0; kl < KT; kl++) mt = fmaxf(mt, srow[kl * 8]);
            if (mt > -INFINITY) {
                float m_new = fmaxf(m_run, mt);
                float alpha = __expf(m_run - m_new);   // m_run=-inf first tile -> 0
                l_run *= alpha;
#pragma unroll
                for (int d = 0; d < 8; d++) o[d] *= alpha;
#pragma unroll
                for (int kl = 0; kl < KT; kl++) {
                    float p = __expf(srow[kl * 8] - m_new);
                    l_run += p;
#pragma unroll
                    for (int d = 0; d < 8; d++) {
                        int r = d * 32 + ch * 4 + cds;
                        o[d] = fmaf(p, v_t[r * 33 + kl], o[d]);
                    }
                }
                m_run = m_new;
            }
        }
        __syncthreads();
    }

    // ---- epilogue: normalize and store [B,Q,E] (e = h*32 + ds*8 + d) ----
    int qg = q0 + cq;
    if (qg < Qn) {
        float inv = 1.f / l_run;
        float* dst = &g_att[(size_t)((b * Qn) + qg) * En + ch * 32 + cds * 8];
        float4 o0 = make_float4(o[0] * inv, o[1] * inv, o[2] * inv, o[3] * inv);
        float4 o1 = make_float4(o[4] * inv, o[5] * inv, o[6] * inv, o[7] * inv);
        *(float4*)dst       = o0;
        *(float4*)(dst + 4) = o1;
    }
}

// ---------------- launch ----------------
extern "C" void kernel_launch(void* const* d_in, const int* in_sizes, int n_in,
                              void* d_out, int out_size)
{
    const float*         nodes  = (const float*)d_in[0];
    const float*         images = (const float*)d_in[1];
    const unsigned char* imask  = (const unsigned char*)d_in[2];
    const float*         rd     = (const float*)d_in[3];
    const float*         Wq     = (const float*)d_in[4];
    const float*         bq     = (const float*)d_in[5];
    const float*         Wkv    = (const float*)d_in[6];
    const float*         bkv    = (const float*)d_in[7];
    const float*         Wc1    = (const float*)d_in[8];
    const float*         bc1    = (const float*)d_in[9];
    const float*         Wc2    = (const float*)d_in[10];
    const float*         bc2    = (const float*)d_in[11];
    const float*         Wo     = (const float*)d_in[12];
    const float*         bo     = (const float*)d_in[13];
    float*               out    = (float*)d_out;

    float *pq, *pk, *pv, *pa;
    cudaGetSymbolAddress((void**)&pq, g_q);
    cudaGetSymbolAddress((void**)&pk, g_k);
    cudaGetSymbolAddress((void**)&pv, g_v);
    cudaGetSymbolAddress((void**)&pa, g_att);

    const int MQ = Bn * Qn;   // 3600
    const int MK = Bn * Kn;   // 4096

    // q projection (pre-scaled by 1/sqrt(D))
    {
        dim3 g((MQ + 63) / 64, 4);
        proj_gemm<<<g, 256>>>(nodes, Wq, bq, pq, MQ, SCALE_Q);
    }
    // k / v projections
    {
        dim3 g((MK + 63) / 64, 4);
        proj_gemm<<<g, 256>>>(images, Wkv,            bkv,       pk, MK, 1.f);
        proj_gemm<<<g, 256>>>(images, Wkv + 256 * 256, bkv + 256, pv, MK, 1.f);
    }
    // fused attention
    {
        cudaFuncSetAttribute(attn_kernel,
                             cudaFuncAttributeMaxDynamicSharedMemorySize, SM_BYTES);
        dim3 g((Qn + QT - 1) / QT, Bn);   // (113, 4)
        attn_kernel<<<g, 256, SM_BYTES>>>(rd, imask, Wc1, bc1, Wc2, bc2);
    }
    // output projection
    {
        dim3 g((MQ + 63) / 64, 4);
        proj_gemm<<<g, 256>>>(pa, Wo, bo, out, MQ, 1.f);
    }
}

// round 2
// speedup vs baseline: 1.0839x; 1.0839x over previous
#include <cuda_runtime.h>
#include <cuda_bf16.h>
#include <math.h>

// ---------------- problem constants ----------------
#define Bn 4
#define Qn 900
#define Kn 1024
#define En 256
#define Hn 8
#define Dn 32
#define QT 8
#define KT 32
#define SCALE_Q 0.17677669529663687f  // 1/sqrt(32)

// ---------------- scratch ----------------
__device__ __align__(16) float g_q[Bn * Qn * En];
__device__ __align__(16) float g_k[Bn * Kn * En];
__device__ __align__(16) float g_v[Bn * Kn * En];
__device__ __align__(16) float g_att[Bn * Qn * En];

// ---------------- projection GEMM (unchanged) ----------------
__global__ __launch_bounds__(256) void proj_gemm(
    const float* __restrict__ A, const float* __restrict__ W,
    const float* __restrict__ bias, float* __restrict__ C,
    int M, float scale)
{
    __shared__ __align__(16) float As[16][64];
    __shared__ __align__(16) float Bs[16][64];

    const int m0 = blockIdx.x * 64;
    const int n0 = blockIdx.y * 64;
    const int t  = threadIdx.x;
    const int tx = t & 15;
    const int ty = t >> 4;
    const int lr = t >> 2;
    const int lc = (t & 3) * 4;

    float acc[4][4];
#pragma unroll
    for (int i = 0; i < 4; i++)
#pragma unroll
        for (int j = 0; j < 4; j++) acc[i][j] = 0.f;

    for (int k0 = 0; k0 < 256; k0 += 16) {
        float4 a4 = make_float4(0.f, 0.f, 0.f, 0.f);
        if (m0 + lr < M)
            a4 = *(const float4*)&A[(size_t)(m0 + lr) * 256 + k0 + lc];
        As[lc + 0][lr] = a4.x; As[lc + 1][lr] = a4.y;
        As[lc + 2][lr] = a4.z; As[lc + 3][lr] = a4.w;

        float4 b4 = *(const float4*)&W[(size_t)(n0 + lr) * 256 + k0 + lc];
        Bs[lc + 0][lr] = b4.x; Bs[lc + 1][lr] = b4.y;
        Bs[lc + 2][lr] = b4.z; Bs[lc + 3][lr] = b4.w;
        __syncthreads();

#pragma unroll
        for (int kk = 0; kk < 16; kk++) {
            float4 av = *(const float4*)&As[kk][ty * 4];
            float4 bv = *(const float4*)&Bs[kk][tx * 4];
            float am[4] = {av.x, av.y, av.z, av.w};
            float bm[4] = {bv.x, bv.y, bv.z, bv.w};
#pragma unroll
            for (int i = 0; i < 4; i++)
#pragma unroll
                for (int j = 0; j < 4; j++)
                    acc[i][j] = fmaf(am[i], bm[j], acc[i][j]);
        }
        __syncthreads();
    }

#pragma unroll
    for (int i = 0; i < 4; i++) {
        int m = m0 + ty * 4 + i;
        if (m < M) {
            int n = n0 + tx * 4;
            float4 o;
            o.x = scale * (acc[i][0] + bias[n + 0]);
            o.y = scale * (acc[i][1] + bias[n + 1]);
            o.z = scale * (acc[i][2] + bias[n + 2]);
            o.w = scale * (acc[i][3] + bias[n + 3]);
            *(float4*)&C[(size_t)m * 256 + n] = o;
        }
    }
}

// ---------------- fused attention ----------------
// SMEM layout (floats), all rows stride-260 (=65*4 -> conflict-free LDS.128 patterns)
#define SM_Q    0                    // [8][260]   2080
#define SM_K    2080                 // [32][260]  8320
#define SM_V    10400                // [32][260]  8320
#define SM_CPB  18720                // [8][8][33] 2112
#define SM_P    20832                // [8][8][33] 2112
#define SM_MT   22944                // [8][8]       64
#define SM_LT   23008                // [8][8]       64
#define SM_W1   23072                // float4[64]  256
#define SM_W2   23328                // [64][8]     512
#define SM_B2   23840                // [8]           8
#define SM_FLOATS 23848
#define SM_BYTES (SM_FLOATS * 4)
#define NEG_BIG (-1e30f)

__global__ __launch_bounds__(256, 2) void attn_kernel(
    const float* __restrict__ rd, const unsigned char* __restrict__ mask,
    const float* __restrict__ Wc1, const float* __restrict__ bc1,
    const float* __restrict__ Wc2, const float* __restrict__ bc2)
{
    extern __shared__ __align__(16) float sm[];
    float*  q_s  = sm + SM_Q;
    float*  k_s  = sm + SM_K;
    float*  v_s  = sm + SM_V;
    float*  cpb  = sm + SM_CPB;
    float*  p_s  = sm + SM_P;
    float*  mt_s = sm + SM_MT;
    float*  lt_s = sm + SM_LT;
    float4* w1   = (float4*)(sm + SM_W1);
    float*  w2   = sm + SM_W2;
    float*  b2   = sm + SM_B2;

    const int b  = blockIdx.y;
    const int q0 = blockIdx.x * QT;
    const int t  = threadIdx.x;

    // ---- prologue: load q tile (stride 260) + CPB weights ----
#pragma unroll
    for (int i = 0; i < 2; i++) {
        int idx = t + i * 256;        // 512 float4 = 8 rows x 64 chunks
        int qq  = idx >> 6, e4 = idx & 63;
        float4 val = make_float4(0.f, 0.f, 0.f, 0.f);
        if (q0 + qq < Qn)
            val = *(const float4*)&g_q[(size_t)((b * Qn) + (q0 + qq)) * En + e4 * 4];
        *(float4*)&q_s[qq * 260 + e4 * 4] = val;
    }
    if (t < 64) w1[t] = make_float4(Wc1[2 * t], Wc1[2 * t + 1], bc1[t], 0.f);
    for (int i = t; i < 512; i += 256) {
        int j = i >> 3, h = i & 7;
        w2[j * 8 + h] = Wc2[h * 64 + j];
    }
    if (t < 8) b2[t] = bc2[t];
    __syncthreads();

    // ---- persistent per-thread state for phase C: thread = (cq, eg) ----
    const int cq = t >> 5;
    const int eg = t & 31;
    const int h1 = eg >> 3;       // dims eg*4..+3   -> head h1
    const int h2 = h1 + 4;        // dims 128+eg*4.. -> head h2
    float m1 = -INFINITY, l1 = 0.f;
    float m2 = -INFINITY, l2 = 0.f;
    float o[8];
#pragma unroll
    for (int d = 0; d < 8; d++) o[d] = 0.f;

    // phase B identities
    const int bq  = t >> 5;       // B1: query
    const int bk  = t & 31;       // B1: key lane
    const int wh  = t >> 5;       // B2: head (warp)
    const int wk  = t & 31;       // B2: key (lane)

    for (int k0 = 0; k0 < Kn; k0 += KT) {
        // ===== Phase A: load K/V tile into stride-260 rows =====
#pragma unroll
        for (int i = 0; i < 8; i++) {
            int idx = t + i * 256;     // 2048 float4 = 32 rows x 64 chunks
            int kk  = idx >> 6, e4 = idx & 63;
            size_t gidx = (size_t)((b * Kn) + (k0 + kk)) * En + e4 * 4;
            *(float4*)&k_s[kk * 260 + e4 * 4] = *(const float4*)&g_k[gidx];
            *(float4*)&v_s[kk * 260 + e4 * 4] = *(const float4*)&g_v[gidx];
        }

        // ===== Phase B1: CPB MLP, shared across heads (overlaps with A) =====
        {
            float acc[8];
#pragma unroll
            for (int h = 0; h < 8; h++) acc[h] = b2[h];

            int qg = q0 + bq;
            float dx = 0.f, dy = 0.f;
            if (qg < Qn) {
                const float2 rd2 = *(const float2*)&rd[(((size_t)b * Qn + qg) * Kn + (k0 + bk)) * 2];
                dx = rd2.x; dy = rd2.y;
            }
#pragma unroll
            for (int j = 0; j < 64; j++) {
                float4 w = w1[j];
                float hj = fmaxf(fmaf(w.x, dx, fmaf(w.y, dy, w.z)), 0.f);
                float4 w2a = *(const float4*)&w2[j * 8];
                float4 w2b = *(const float4*)&w2[j * 8 + 4];
                acc[0] = fmaf(w2a.x, hj, acc[0]);
                acc[1] = fmaf(w2a.y, hj, acc[1]);
                acc[2] = fmaf(w2a.z, hj, acc[2]);
                acc[3] = fmaf(w2a.w, hj, acc[3]);
                acc[4] = fmaf(w2b.x, hj, acc[4]);
                acc[5] = fmaf(w2b.y, hj, acc[5]);
                acc[6] = fmaf(w2b.z, hj, acc[6]);
                acc[7] = fmaf(w2b.w, hj, acc[7]);
            }
            const bool masked = mask[b * Kn + k0 + bk] != 0;
#pragma unroll
            for (int h = 0; h < 8; h++)
                cpb[(bq * 8 + h) * 33 + bk] = masked ? NEG_BIG : acc[h];
        }
        __syncthreads();

        // ===== Phase B2: QK scores, tile softmax stats, exp =====
        {
            float kf[32];
#pragma unroll
            for (int i = 0; i < 8; i++) {
                float4 v4 = *(const float4*)&k_s[wk * 260 + wh * 32 + i * 4];
                kf[i * 4 + 0] = v4.x; kf[i * 4 + 1] = v4.y;
                kf[i * 4 + 2] = v4.z; kf[i * 4 + 3] = v4.w;
            }
            float pv[8], mt[8], lt[8];
#pragma unroll
            for (int q = 0; q < 8; q++) {
                float dot = 0.f;
#pragma unroll
                for (int i = 0; i < 8; i++) {
                    float4 qv = *(const float4*)&q_s[q * 260 + wh * 32 + i * 4];
                    dot = fmaf(qv.x, kf[i * 4 + 0], dot);
                    dot = fmaf(qv.y, kf[i * 4 + 1], dot);
                    dot = fmaf(qv.z, kf[i * 4 + 2], dot);
                    dot = fmaf(qv.w, kf[i * 4 + 3], dot);
                }
                float sc = dot + cpb[(q * 8 + wh) * 33 + wk];
                float m = sc;
#pragma unroll
                for (int off = 16; off; off >>= 1)
                    m = fmaxf(m, __shfl_xor_sync(0xffffffffu, m, off));
                float p = __expf(sc - m);
                float l = p;
#pragma unroll
                for (int off = 16; off; off >>= 1)
                    l += __shfl_xor_sync(0xffffffffu, l, off);
                pv[q] = p; mt[q] = m; lt[q] = l;
            }
#pragma unroll
            for (int q = 0; q < 8; q++)
                p_s[(q * 8 + wh) * 33 + wk] = pv[q];
            if (wk == 0) {
#pragma unroll
                for (int q = 0; q < 8; q++) {
                    mt_s[q * 8 + wh] = mt[q];
                    lt_s[q * 8 + wh] = lt[q];
                }
            }
        }
        __syncthreads();

        // ===== Phase C: AV accumulate + online merge =====
        {
            float ta[8];
#pragma unroll
            for (int d = 0; d < 8; d++) ta[d] = 0.f;
            const float* p1row = &p_s[(cq * 8 + h1) * 33];
            const float* p2row = &p_s[(cq * 8 + h2) * 33];
#pragma unroll
            for (int kl = 0; kl < KT; kl++) {
                float pa = p1row[kl];
                float pb = p2row[kl];
                float4 v1 = *(const float4*)&v_s[kl * 260 + eg * 4];
                float4 v2 = *(const float4*)&v_s[kl * 260 + 128 + eg * 4];
                ta[0] = fmaf(pa, v1.x, ta[0]);
                ta[1] = fmaf(pa, v1.y, ta[1]);
                ta[2] = fmaf(pa, v1.z, ta[2]);
                ta[3] = fmaf(pa, v1.w, ta[3]);
                ta[4] = fmaf(pb, v2.x, ta[4]);
                ta[5] = fmaf(pb, v2.y, ta[5]);
                ta[6] = fmaf(pb, v2.z, ta[6]);
                ta[7] = fmaf(pb, v2.w, ta[7]);
            }
            // merge head-half 1
            {
                float m_t = mt_s[cq * 8 + h1], l_t = lt_s[cq * 8 + h1];
                float m_new = fmaxf(m1, m_t);
                float alpha = __expf(m1 - m_new);
                float beta  = __expf(m_t - m_new);
                l1 = l1 * alpha + l_t * beta;
#pragma unroll
                for (int d = 0; d < 4; d++) o[d] = o[d] * alpha + ta[d] * beta;
                m1 = m_new;
            }
            // merge head-half 2
            {
                float m_t = mt_s[cq * 8 + h2], l_t = lt_s[cq * 8 + h2];
                float m_new = fmaxf(m2, m_t);
                float alpha = __expf(m2 - m_new);
                float beta  = __expf(m_t - m_new);
                l2 = l2 * alpha + l_t * beta;
#pragma unroll
                for (int d = 4; d < 8; d++) o[d] = o[d] * alpha + ta[d] * beta;
                m2 = m_new;
            }
        }
        __syncthreads();
    }

    // ---- epilogue ----
    int qg = q0 + cq;
    if (qg < Qn) {
        float inv1 = 1.f / l1, inv2 = 1.f / l2;
        float* dst = &g_att[(size_t)((b * Qn) + qg) * En];
        *(float4*)&dst[eg * 4] =
            make_float4(o[0] * inv1, o[1] * inv1, o[2] * inv1, o[3] * inv1);
        *(float4*)&dst[128 + eg * 4] =
            make_float4(o[4] * inv2, o[5] * inv2, o[6] * inv2, o[7] * inv2);
    }
}

// ---------------- launch ----------------
extern "C" void kernel_launch(void* const* d_in, const int* in_sizes, int n_in,
                              void* d_out, int out_size)
{
    const float*         nodes  = (const float*)d_in[0];
    const float*         images = (const float*)d_in[1];
    const unsigned char* imask  = (const unsigned char*)d_in[2];
    const float*         rd     = (const float*)d_in[3];
    const float*         Wq     = (const float*)d_in[4];
    const float*         bq     = (const float*)d_in[5];
    const float*         Wkv    = (const float*)d_in[6];
    const float*         bkv    = (const float*)d_in[7];
    const float*         Wc1    = (const float*)d_in[8];
    const float*         bc1    = (const float*)d_in[9];
    const float*         Wc2    = (const float*)d_in[10];
    const float*         bc2    = (const float*)d_in[11];
    const float*         Wo     = (const float*)d_in[12];
    const float*         bo     = (const float*)d_in[13];
    float*               out    = (float*)d_out;

    float *pq, *pk, *pv, *pa;
    cudaGetSymbolAddress((void**)&pq, g_q);
    cudaGetSymbolAddress((void**)&pk, g_k);
    cudaGetSymbolAddress((void**)&pv, g_v);
    cudaGetSymbolAddress((void**)&pa, g_att);

    const int MQ = Bn * Qn;   // 3600
    const int MK = Bn * Kn;   // 4096

    {
        dim3 g((MQ + 63) / 64, 4);
        proj_gemm<<<g, 256>>>(nodes, Wq, bq, pq, MQ, SCALE_Q);
    }
    {
        dim3 g((MK + 63) / 64, 4);
        proj_gemm<<<g, 256>>>(images, Wkv,             bkv,       pk, MK, 1.f);
        proj_gemm<<<g, 256>>>(images, Wkv + 256 * 256, bkv + 256, pv, MK, 1.f);
    }
    {
        cudaFuncSetAttribute(attn_kernel,
                             cudaFuncAttributeMaxDynamicSharedMemorySize, SM_BYTES);
        dim3 g((Qn + QT - 1) / QT, Bn);   // (113, 4)
        attn_kernel<<<g, 256, SM_BYTES>>>(rd, imask, Wc1, bc1, Wc2, bc2);
    }
    {
        dim3 g((MQ + 63) / 64, 4);
        proj_gemm<<<g, 256>>>(pa, Wo, bo, out, MQ, 1.f);
    }
}